// round 14
// baseline (speedup 1.0000x reference)
#include <cuda_runtime.h>

#define DIM      4096
#define B        8
#define KV_DIM   1024   // N_KV_HEADS * HEAD_DIM
#define TOTAL    16384

// Scratch (allocation-free rule: __device__ globals)
__device__ __align__(16) float g_x[B * KV_DIM];  // up-proj result  [b][r]
__device__ __align__(16) float g_y[B * DIM];     // down-proj result [b][o]

__device__ __forceinline__ float dot4(float4 a, float4 b) {
    return a.x * b.x + a.y * b.y + a.z * b.z + a.w * b.w;
}

// ---------------------------------------------------------------------------
// Kernel 1: x[b][r] = sum_k emb[b][k] * Wup[r][k]
// ONE row per 256-thread block, grid = 1024.
// Each thread: 4 independent front-batched DRAM loads (w[0..3], nothing
// between them) + 32 L1-hit emb loads + 128 FMAs. Latency is hidden by
// chip-wide thread count, not per-thread pipelining.
// ---------------------------------------------------------------------------
__global__ void __launch_bounds__(256) up_proj_kernel(
    const float* __restrict__ emb, const float* __restrict__ Wup)
{
    const int tid  = threadIdx.x;
    const int lane = tid & 31;
    const int wid  = tid >> 5;          // 0..7
    const int r    = blockIdx.x;        // row 0..1023
    const float4* w4 = reinterpret_cast<const float4*>(Wup + (size_t)r * DIM);
    const float4* e4 = reinterpret_cast<const float4*>(emb);

    // 4 independent DRAM loads, front-batched (q = s*256 + tid).
    float4 w[4];
#pragma unroll
    for (int s = 0; s < 4; s++) w[s] = __ldg(&w4[s * 256 + tid]);

    float acc[B];
#pragma unroll
    for (int b = 0; b < B; b++) acc[b] = 0.f;

#pragma unroll
    for (int s = 0; s < 4; s++) {
        const int q = s * 256 + tid;
#pragma unroll
        for (int b = 0; b < B; b++) {
            const float4 e = __ldg(&e4[(size_t)b * 1024 + q]);
            acc[b] += dot4(w[s], e);
        }
    }

    // warp shuffle reduce, then cross-warp combine
    __shared__ float s_part[8][B];      // [warp][b]
#pragma unroll
    for (int b = 0; b < B; b++) {
        float v = acc[b];
#pragma unroll
        for (int off = 16; off; off >>= 1) v += __shfl_down_sync(0xffffffffu, v, off);
        if (lane == 0) s_part[wid][b] = v;
    }
    __syncthreads();
    if (tid < B) {                      // tid = b
        float v = 0.f;
#pragma unroll
        for (int w8 = 0; w8 < 8; w8++) v += s_part[w8][tid];
        g_x[tid * KV_DIM + r] = v;
    }
}

// ---------------------------------------------------------------------------
// Kernel 2: y[b][o] = sum_j val[b][j] * Wdown[o][j]
//   val[b][j] = x[b][((j>>9)<<7)|(j&127)]  (repeat-interleave remap).
// ONE row per 256-thread block, grid = 4096 (~27 CTAs/SM queued).
// Wdown (64 MB) read exactly once with 4 front-batched loads per thread;
// g_x (32 KB) is L1-resident.
// ---------------------------------------------------------------------------
__global__ void __launch_bounds__(256) down_proj_kernel(
    const float* __restrict__ Wdown)
{
    const int tid  = threadIdx.x;
    const int lane = tid & 31;
    const int wid  = tid >> 5;          // 0..7
    const int o    = blockIdx.x;        // row 0..4095
    const float4* w4 = reinterpret_cast<const float4*>(Wdown + (size_t)o * DIM);

    float4 w[4];
#pragma unroll
    for (int s = 0; s < 4; s++) w[s] = __ldg(&w4[s * 256 + tid]);

    float acc[B];
#pragma unroll
    for (int b = 0; b < B; b++) acc[b] = 0.f;

#pragma unroll
    for (int s = 0; s < 4; s++) {
        const int q  = s * 256 + tid;
        const int j0 = 4 * q;
        const int m0 = ((j0 >> 9) << 7) | (j0 & 127);    // remap, float4-aligned
#pragma unroll
        for (int b = 0; b < B; b++) {
            const float4 xv = *reinterpret_cast<const float4*>(&g_x[b * KV_DIM + m0]);
            acc[b] += dot4(w[s], xv);
        }
    }

    __shared__ float s_part[8][B];
#pragma unroll
    for (int b = 0; b < B; b++) {
        float v = acc[b];
#pragma unroll
        for (int off = 16; off; off >>= 1) v += __shfl_down_sync(0xffffffffu, v, off);
        if (lane == 0) s_part[wid][b] = v;
    }
    __syncthreads();
    if (tid < B) {                      // tid = b
        float v = 0.f;
#pragma unroll
        for (int w8 = 0; w8 < 8; w8++) v += s_part[w8][tid];
        g_y[tid * DIM + o] = v;
    }
}

// ---------------------------------------------------------------------------
// Kernel 3: out[t][:] = y[batch(t)][:]  — 256 MB, HBM-write-bound (floor).
// One token per 128-thread half-block: 128 threads x 8 float4 = exactly one
// full 16 KB row, contiguous streaming stores. Adjacent half-blocks write
// adjacent rows. y (128 KB) is L1-resident so reads ride under the writes.
// grid = 8192 blocks x 256 threads (2 tokens per block).
// ---------------------------------------------------------------------------
__global__ void __launch_bounds__(256) broadcast_kernel(
    const int* __restrict__ seqlen_raw, float* __restrict__ out)
{
    __shared__ int s_off[B + 1];
    if (threadIdx.x == 0) {
        int sum32 = 0;
#pragma unroll
        for (int i = 0; i < B; i++) sum32 += seqlen_raw[i];
        const bool is64 = (sum32 != TOTAL);   // int64: low word at 2*i (LE)
        int acc = 0;
#pragma unroll
        for (int i = 0; i < B; i++) {
            s_off[i] = acc;
            acc += is64 ? seqlen_raw[2 * i] : seqlen_raw[i];
        }
        s_off[B] = acc;
    }
    __syncthreads();

    const int sub   = threadIdx.x & 127;                      // 0..127
    const int token = blockIdx.x * 2 + (threadIdx.x >> 7);    // one token per half-block

    int b = 0;
#pragma unroll
    for (int i = 1; i < B; i++) b += (token >= s_off[i]);

    const float4* y4 = reinterpret_cast<const float4*>(&g_y[b * DIM]);
    float4* o4 = reinterpret_cast<float4*>(out) + (size_t)token * 1024;

    float4 v[8];
#pragma unroll
    for (int k = 0; k < 8; k++) v[k] = __ldg(&y4[sub + k * 128]);
#pragma unroll
    for (int k = 0; k < 8; k++) __stcs(&o4[sub + k * 128], v[k]);
}

// ---------------------------------------------------------------------------
// Inputs (metadata order): embedding [8,4096] f32, W_up [1024,4096] f32,
// W_down [4096,4096] f32, seqlen [8] int. Output: [16384,4096] f32.
// ---------------------------------------------------------------------------
extern "C" void kernel_launch(void* const* d_in, const int* in_sizes, int n_in,
                              void* d_out, int out_size)
{
    const float* emb    = (const float*)d_in[0];
    const float* Wup    = (const float*)d_in[1];
    const float* Wdown  = (const float*)d_in[2];
    const int*   seqlen = (const int*)d_in[3];
    float* out = (float*)d_out;

    up_proj_kernel<<<KV_DIM, 256>>>(emb, Wup);
    down_proj_kernel<<<DIM, 256>>>(Wdown);
    broadcast_kernel<<<TOTAL / 2, 256>>>(seqlen, out);
}

// round 15
// speedup vs baseline: 1.0554x; 1.0554x over previous
#include <cuda_runtime.h>

#define DIM      4096
#define B        8
#define KV_DIM   1024   // N_KV_HEADS * HEAD_DIM
#define TOTAL    16384

// Scratch (allocation-free rule: __device__ globals)
__device__ __align__(16) float g_x[B * KV_DIM];  // up-proj result  [b][r]
__device__ __align__(16) float g_y[B * DIM];     // down-proj result [b][o]

__device__ __forceinline__ float dot4(float4 a, float4 b) {
    return a.x * b.x + a.y * b.y + a.z * b.z + a.w * b.w;
}

// ---------------------------------------------------------------------------
// Kernel 1: x[b][r] = sum_k emb[b][k] * Wup[r][k]
// (Measured-best config from R13: 2 rows/block, grid=512, 256 threads.)
// ---------------------------------------------------------------------------
__global__ void __launch_bounds__(256) up_proj_kernel(
    const float* __restrict__ emb, const float* __restrict__ Wup)
{
    const int tid  = threadIdx.x;
    const int lane = tid & 31;
    const int wid  = tid >> 5;          // 0..7 : k-slice
    const int r0   = blockIdx.x * 2;    // rows r0, r0+1
    const float4* w4 = reinterpret_cast<const float4*>(Wup);
    const float4* e4 = reinterpret_cast<const float4*>(emb);

    float acc[2][B];
#pragma unroll
    for (int i = 0; i < 2; i++)
#pragma unroll
        for (int b = 0; b < B; b++) acc[i][b] = 0.f;

#pragma unroll
    for (int s = 0; s < 4; s++) {
        const int q = wid * 128 + s * 32 + lane;   // float4 idx in [0,1024)
        const float4 w0 = __ldg(&w4[(size_t)r0 * 1024 + q]);
        const float4 w1 = __ldg(&w4[(size_t)(r0 + 1) * 1024 + q]);
#pragma unroll
        for (int b = 0; b < B; b++) {
            const float4 e = __ldg(&e4[(size_t)b * 1024 + q]);
            acc[0][b] += dot4(w0, e);
            acc[1][b] += dot4(w1, e);
        }
    }

    __shared__ float s_part[8][2][B];   // [warp][row][b]
#pragma unroll
    for (int i = 0; i < 2; i++)
#pragma unroll
        for (int b = 0; b < B; b++) {
            float v = acc[i][b];
#pragma unroll
            for (int off = 16; off; off >>= 1) v += __shfl_down_sync(0xffffffffu, v, off);
            if (lane == 0) s_part[wid][i][b] = v;
        }
    __syncthreads();
    if (tid < 16) {
        const int row = tid >> 3, b = tid & 7;
        float v = 0.f;
#pragma unroll
        for (int w8 = 0; w8 < 8; w8++) v += s_part[w8][row][b];
        g_x[b * KV_DIM + r0 + row] = v;
    }
}

// ---------------------------------------------------------------------------
// Kernel 2: y[b][o] = sum_j val[b][j] * Wdown[o][j]
//   val[b][j] = x[b][((j>>9)<<7)|(j&127)]  (repeat-interleave remap).
//
// KEY: the remap DROPS bits 7-8 of j0, so the four q positions
//   q = 128*c + t + 32*u   (u = 0..3)
// all read the SAME x chunk m0 = 128*c + 4*t. Thread (warp c, lane t) loads
// its 8 x float4s ONCE into registers and reuses them against 4 W chunks:
// per thread: 8 x-loads + 8 W-loads + 32 dot4  (was 32 x-loads + 8 W-loads).
// L1 wavefronts per block drop 1152 -> 512.
// 2 rows per block, grid = 2048, 256 threads. Wdown (64 MB) read once.
// ---------------------------------------------------------------------------
__global__ void __launch_bounds__(256) down_proj_kernel(
    const float* __restrict__ Wdown)
{
    const int tid  = threadIdx.x;
    const int lane = tid & 31;          // t
    const int wid  = tid >> 5;          // c : 512-float j-chunk
    const int r0   = blockIdx.x * 2;    // rows r0, r0+1 of 4096
    const float4* w4 = reinterpret_cast<const float4*>(Wdown);

    // x float4 index for this thread (same for all 4 u): m0/4 = 32*c + t
    const int xi = wid * 32 + lane;
    float4 xv[B];
#pragma unroll
    for (int b = 0; b < B; b++)
        xv[b] = *reinterpret_cast<const float4*>(&g_x[b * KV_DIM + 4 * xi]);

    float acc[2][B];
#pragma unroll
    for (int i = 0; i < 2; i++)
#pragma unroll
        for (int b = 0; b < B; b++) acc[i][b] = 0.f;

#pragma unroll
    for (int u = 0; u < 4; u++) {
        const int q = wid * 128 + lane + 32 * u;   // float4 idx in [0,1024)
        const float4 w0 = __ldg(&w4[(size_t)r0 * 1024 + q]);
        const float4 w1 = __ldg(&w4[(size_t)(r0 + 1) * 1024 + q]);
#pragma unroll
        for (int b = 0; b < B; b++) {
            acc[0][b] += dot4(w0, xv[b]);
            acc[1][b] += dot4(w1, xv[b]);
        }
    }

    __shared__ float s_part[8][2][B];
#pragma unroll
    for (int i = 0; i < 2; i++)
#pragma unroll
        for (int b = 0; b < B; b++) {
            float v = acc[i][b];
#pragma unroll
            for (int off = 16; off; off >>= 1) v += __shfl_down_sync(0xffffffffu, v, off);
            if (lane == 0) s_part[wid][i][b] = v;
        }
    __syncthreads();
    if (tid < 16) {
        const int row = tid >> 3, b = tid & 7;
        float v = 0.f;
#pragma unroll
        for (int w8 = 0; w8 < 8; w8++) v += s_part[w8][row][b];
        g_y[b * DIM + r0 + row] = v;
    }
}

// ---------------------------------------------------------------------------
// Kernel 3: out[t][:] = y[batch(t)][:]  — 256 MB, HBM-write-bound (floor).
// One token per 128-thread half-block: 128 threads x 8 float4 = exactly one
// full 16 KB row, contiguous streaming stores. y (128 KB) is L1-resident.
// grid = 8192 blocks x 256 threads (2 tokens per block).
// ---------------------------------------------------------------------------
__global__ void __launch_bounds__(256) broadcast_kernel(
    const int* __restrict__ seqlen_raw, float* __restrict__ out)
{
    __shared__ int s_off[B + 1];
    if (threadIdx.x == 0) {
        int sum32 = 0;
#pragma unroll
        for (int i = 0; i < B; i++) sum32 += seqlen_raw[i];
        const bool is64 = (sum32 != TOTAL);   // int64: low word at 2*i (LE)
        int acc = 0;
#pragma unroll
        for (int i = 0; i < B; i++) {
            s_off[i] = acc;
            acc += is64 ? seqlen_raw[2 * i] : seqlen_raw[i];
        }
        s_off[B] = acc;
    }
    __syncthreads();

    const int sub   = threadIdx.x & 127;                      // 0..127
    const int token = blockIdx.x * 2 + (threadIdx.x >> 7);    // one token per half-block

    int b = 0;
#pragma unroll
    for (int i = 1; i < B; i++) b += (token >= s_off[i]);

    const float4* y4 = reinterpret_cast<const float4*>(&g_y[b * DIM]);
    float4* o4 = reinterpret_cast<float4*>(out) + (size_t)token * 1024;

    float4 v[8];
#pragma unroll
    for (int k = 0; k < 8; k++) v[k] = __ldg(&y4[sub + k * 128]);
#pragma unroll
    for (int k = 0; k < 8; k++) __stcs(&o4[sub + k * 128], v[k]);
}

// ---------------------------------------------------------------------------
// Inputs (metadata order): embedding [8,4096] f32, W_up [1024,4096] f32,
// W_down [4096,4096] f32, seqlen [8] int. Output: [16384,4096] f32.
// ---------------------------------------------------------------------------
extern "C" void kernel_launch(void* const* d_in, const int* in_sizes, int n_in,
                              void* d_out, int out_size)
{
    const float* emb    = (const float*)d_in[0];
    const float* Wup    = (const float*)d_in[1];
    const float* Wdown  = (const float*)d_in[2];
    const int*   seqlen = (const int*)d_in[3];
    float* out = (float*)d_out;

    up_proj_kernel<<<KV_DIM / 2, 256>>>(emb, Wup);
    down_proj_kernel<<<DIM / 2, 256>>>(Wdown);
    broadcast_kernel<<<TOTAL / 2, 256>>>(seqlen, out);
}

// round 16
// speedup vs baseline: 1.1899x; 1.1274x over previous
#include <cuda_runtime.h>

#define DIM      4096
#define B        8
#define KV_DIM   1024   // N_KV_HEADS * HEAD_DIM
#define TOTAL    16384

// Scratch (allocation-free rule: __device__ globals)
__device__ __align__(16) float g_x[B * KV_DIM];  // up-proj result  [b][r]
__device__ __align__(16) float g_y[B * DIM];     // down-proj result [b][o]

__device__ __forceinline__ float dot4(float4 a, float4 b) {
    return a.x * b.x + a.y * b.y + a.z * b.z + a.w * b.w;
}

// ---------------------------------------------------------------------------
// Kernel 1: x[b][r] = sum_k emb[b][k] * Wup[r][k]
// (Measured-best config: 2 rows/block, grid=512, 256 threads.)
// ---------------------------------------------------------------------------
__global__ void __launch_bounds__(256) up_proj_kernel(
    const float* __restrict__ emb, const float* __restrict__ Wup)
{
    const int tid  = threadIdx.x;
    const int lane = tid & 31;
    const int wid  = tid >> 5;          // 0..7 : k-slice
    const int r0   = blockIdx.x * 2;    // rows r0, r0+1
    const float4* w4 = reinterpret_cast<const float4*>(Wup);
    const float4* e4 = reinterpret_cast<const float4*>(emb);

    float acc[2][B];
#pragma unroll
    for (int i = 0; i < 2; i++)
#pragma unroll
        for (int b = 0; b < B; b++) acc[i][b] = 0.f;

#pragma unroll
    for (int s = 0; s < 4; s++) {
        const int q = wid * 128 + s * 32 + lane;   // float4 idx in [0,1024)
        const float4 w0 = __ldg(&w4[(size_t)r0 * 1024 + q]);
        const float4 w1 = __ldg(&w4[(size_t)(r0 + 1) * 1024 + q]);
#pragma unroll
        for (int b = 0; b < B; b++) {
            const float4 e = __ldg(&e4[(size_t)b * 1024 + q]);
            acc[0][b] += dot4(w0, e);
            acc[1][b] += dot4(w1, e);
        }
    }

    __shared__ float s_part[8][2][B];   // [warp][row][b]
#pragma unroll
    for (int i = 0; i < 2; i++)
#pragma unroll
        for (int b = 0; b < B; b++) {
            float v = acc[i][b];
#pragma unroll
            for (int off = 16; off; off >>= 1) v += __shfl_down_sync(0xffffffffu, v, off);
            if (lane == 0) s_part[wid][i][b] = v;
        }
    __syncthreads();
    if (tid < 16) {
        const int row = tid >> 3, b = tid & 7;
        float v = 0.f;
#pragma unroll
        for (int w8 = 0; w8 < 8; w8++) v += s_part[w8][row][b];
        g_x[b * KV_DIM + r0 + row] = v;
    }
}

// ---------------------------------------------------------------------------
// Kernel 2: y[b][o] = sum_j val[b][j] * Wdown[o][j]
//   val[b][j] = x[b][((j>>9)<<7)|(j&127)]  (repeat-interleave remap).
//
// ALGEBRAIC FOLD: for q = 128c + t + 32u (u=0..3), all four W chunks multiply
// the SAME x float4 (the remap drops bits 7-8 of the byte index). So sum the
// four W chunks FIRST (12 FADD), then do ONE dot4 per batch:
//   per thread: 4 front-batched DRAM W loads + 8 L1 x loads + 44 flops.
// The kernel is a near-pure 64 MB DRAM read stream.
// ONE row per 256-thread block, grid = 4096 (~60 regs -> 4 CTAs/SM resident).
// ---------------------------------------------------------------------------
__global__ void __launch_bounds__(256) down_proj_kernel(
    const float* __restrict__ Wdown)
{
    const int tid  = threadIdx.x;
    const int lane = tid & 31;          // t
    const int wid  = tid >> 5;          // c : 512-float j-chunk
    const int o    = blockIdx.x;        // row 0..4095
    const float4* w4 = reinterpret_cast<const float4*>(Wdown + (size_t)o * DIM);

    // 4 independent DRAM loads, front-batched.
    float4 w[4];
#pragma unroll
    for (int u = 0; u < 4; u++) w[u] = __ldg(&w4[wid * 128 + lane + 32 * u]);

    // Fold the repeat group: one summed W chunk.
    float4 ws;
    ws.x = (w[0].x + w[1].x) + (w[2].x + w[3].x);
    ws.y = (w[0].y + w[1].y) + (w[2].y + w[3].y);
    ws.z = (w[0].z + w[1].z) + (w[2].z + w[3].z);
    ws.w = (w[0].w + w[1].w) + (w[2].w + w[3].w);

    // Shared x chunk for this thread: float4 index 32*c + t (L1-resident).
    const int xi = wid * 32 + lane;
    const float4* x4 = reinterpret_cast<const float4*>(g_x);

    float acc[B];
#pragma unroll
    for (int b = 0; b < B; b++)
        acc[b] = dot4(ws, x4[b * 256 + xi]);

    __shared__ float s_part[8][B];      // [warp][b]
#pragma unroll
    for (int b = 0; b < B; b++) {
        float v = acc[b];
#pragma unroll
        for (int off = 16; off; off >>= 1) v += __shfl_down_sync(0xffffffffu, v, off);
        if (lane == 0) s_part[wid][b] = v;
    }
    __syncthreads();
    if (tid < B) {                      // tid = b
        float v = 0.f;
#pragma unroll
        for (int w8 = 0; w8 < 8; w8++) v += s_part[w8][tid];
        g_y[tid * DIM + o] = v;
    }
}

// ---------------------------------------------------------------------------
// Kernel 3: out[t][:] = y[batch(t)][:]  — 256 MB, HBM-write-bound (floor).
// One token per 128-thread half-block: 128 threads x 8 float4 = exactly one
// full 16 KB row, contiguous streaming stores. y (128 KB) is L1-resident.
// grid = 8192 blocks x 256 threads (2 tokens per block).
// ---------------------------------------------------------------------------
__global__ void __launch_bounds__(256) broadcast_kernel(
    const int* __restrict__ seqlen_raw, float* __restrict__ out)
{
    __shared__ int s_off[B + 1];
    if (threadIdx.x == 0) {
        int sum32 = 0;
#pragma unroll
        for (int i = 0; i < B; i++) sum32 += seqlen_raw[i];
        const bool is64 = (sum32 != TOTAL);   // int64: low word at 2*i (LE)
        int acc = 0;
#pragma unroll
        for (int i = 0; i < B; i++) {
            s_off[i] = acc;
            acc += is64 ? seqlen_raw[2 * i] : seqlen_raw[i];
        }
        s_off[B] = acc;
    }
    __syncthreads();

    const int sub   = threadIdx.x & 127;                      // 0..127
    const int token = blockIdx.x * 2 + (threadIdx.x >> 7);    // one token per half-block

    int b = 0;
#pragma unroll
    for (int i = 1; i < B; i++) b += (token >= s_off[i]);

    const float4* y4 = reinterpret_cast<const float4*>(&g_y[b * DIM]);
    float4* o4 = reinterpret_cast<float4*>(out) + (size_t)token * 1024;

    float4 v[8];
#pragma unroll
    for (int k = 0; k < 8; k++) v[k] = __ldg(&y4[sub + k * 128]);
#pragma unroll
    for (int k = 0; k < 8; k++) __stcs(&o4[sub + k * 128], v[k]);
}

// ---------------------------------------------------------------------------
// Inputs (metadata order): embedding [8,4096] f32, W_up [1024,4096] f32,
// W_down [4096,4096] f32, seqlen [8] int. Output: [16384,4096] f32.
// ---------------------------------------------------------------------------
extern "C" void kernel_launch(void* const* d_in, const int* in_sizes, int n_in,
                              void* d_out, int out_size)
{
    const float* emb    = (const float*)d_in[0];
    const float* Wup    = (const float*)d_in[1];
    const float* Wdown  = (const float*)d_in[2];
    const int*   seqlen = (const int*)d_in[3];
    float* out = (float*)d_out;

    up_proj_kernel<<<KV_DIM / 2, 256>>>(emb, Wup);
    down_proj_kernel<<<DIM, 256>>>(Wdown);
    broadcast_kernel<<<TOTAL / 2, 256>>>(seqlen, out);
}